// round 9
// baseline (speedup 1.0000x reference)
#include <cuda_runtime.h>
#include <cuda_bf16.h>
#include <cstdint>

#define BB 2
#define NN 2048
#define DD 512
#define HH 8
#define HD 64
#define ROWS (BB*NN)

// Scratch (no allocations allowed)
__device__ __nv_bfloat16 g_QKV[3][(size_t)ROWS * DD];   // Q,K,V projections
__device__ __nv_bfloat16 g_Xb[(size_t)ROWS * DD];       // x in bf16
__device__ __nv_bfloat16 g_Wb[3][(size_t)DD * DD];      // W_q/k/v in bf16
__device__ float g_c[ROWS];                             // gate vec (log2-scaled)
__device__ float g_maxk[BB * HH];                       // max_j ||k_j|| per (b,h)
__device__ float g_maxc[BB];                            // max_j c_j per batch
__device__ float g_mrow[(size_t)BB * HH * NN];          // per-row exponent bound

#define LOG2E 1.4426950408889634f
#define SCLOG (0.125f * LOG2E)

// ---------------------------------------------------------------------------
// helpers
// ---------------------------------------------------------------------------
__device__ __forceinline__ float ex2f(float x) {        // 2^x on MUFU
    float r;
    asm("ex2.approx.f32 %0, %1;" : "=f"(r) : "f"(x));
    return r;
}
__device__ __forceinline__ uint32_t pack_bf16(float lo, float hi) {
    uint32_t r;
    asm("cvt.rn.bf16x2.f32 %0, %1, %2;" : "=r"(r) : "f"(hi), "f"(lo));
    return r;
}
__device__ __forceinline__ void mma16(float* d, const uint32_t* a,
                                      uint32_t b0, uint32_t b1, const float* c) {
    asm("mma.sync.aligned.m16n8k16.row.col.f32.bf16.bf16.f32 "
        "{%0,%1,%2,%3}, {%4,%5,%6,%7}, {%8,%9}, {%10,%11,%12,%13};"
        : "=f"(d[0]), "=f"(d[1]), "=f"(d[2]), "=f"(d[3])
        : "r"(a[0]), "r"(a[1]), "r"(a[2]), "r"(a[3]),
          "r"(b0), "r"(b1),
          "f"(c[0]), "f"(c[1]), "f"(c[2]), "f"(c[3]));
}
__device__ __forceinline__ void ldm_x4(uint32_t* r, const void* ptr) {
    uint32_t a = (uint32_t)__cvta_generic_to_shared(ptr);
    asm volatile("ldmatrix.sync.aligned.m8n8.x4.shared.b16 "
                 "{%0,%1,%2,%3}, [%4];"
                 : "=r"(r[0]), "=r"(r[1]), "=r"(r[2]), "=r"(r[3]) : "r"(a));
}
__device__ __forceinline__ void ldm_x4_trans(uint32_t* r, const void* ptr) {
    uint32_t a = (uint32_t)__cvta_generic_to_shared(ptr);
    asm volatile("ldmatrix.sync.aligned.m8n8.x4.trans.shared.b16 "
                 "{%0,%1,%2,%3}, [%4];"
                 : "=r"(r[0]), "=r"(r[1]), "=r"(r[2]), "=r"(r[3]) : "r"(a));
}
__device__ __forceinline__ void cpa16(void* smem_dst, const void* gsrc) {
    uint32_t d = (uint32_t)__cvta_generic_to_shared(smem_dst);
    asm volatile("cp.async.cg.shared.global [%0], [%1], 16;" :: "r"(d), "l"(gsrc));
}
#define CP_COMMIT asm volatile("cp.async.commit_group;" ::: "memory")
#define CP_WAIT1  asm volatile("cp.async.wait_group 1;" ::: "memory")
#define CP_WAIT0  asm volatile("cp.async.wait_group 0;" ::: "memory")

// ---------------------------------------------------------------------------
// Kernel 0: one-shot fp32 -> bf16 conversion of x and W_q/k/v.
// ---------------------------------------------------------------------------
__global__ __launch_bounds__(256)
void convert_kernel(const float* __restrict__ X, const float* __restrict__ Wq,
                    const float* __restrict__ Wk, const float* __restrict__ Wv)
{
    int idx = blockIdx.x * 256 + threadIdx.x;
    const float* src;
    __nv_bfloat16* dst;
    size_t off;
    if (idx < 262144) {
        src = X; dst = g_Xb; off = (size_t)idx * 8;
    } else {
        int r = idx - 262144;
        int z = r >> 15;
        int o = r & 32767;
        src = (z == 0) ? Wq : (z == 1) ? Wk : Wv;
        dst = g_Wb[z]; off = (size_t)o * 8;
    }
    float4 v0 = *(const float4*)(src + off);
    float4 v1 = *(const float4*)(src + off + 4);
    uint4 u;
    u.x = pack_bf16(v0.x, v0.y);
    u.y = pack_bf16(v0.z, v0.w);
    u.z = pack_bf16(v1.x, v1.y);
    u.w = pack_bf16(v1.z, v1.w);
    *(uint4*)(dst + off) = u;
}

// ---------------------------------------------------------------------------
// Kernel 1: fused QKV projection, pure bf16, cp.async double-buffered, BK=64.
// ---------------------------------------------------------------------------
__global__ __launch_bounds__(256)
void qkv_gemm(const float* __restrict__ bq, const float* __restrict__ bk,
              const float* __restrict__ bv)
{
    extern __shared__ __nv_bfloat16 dsm[];
    __nv_bfloat16* Xs[2] = {dsm, dsm + 128 * 72};
    __nv_bfloat16* Ws[2] = {dsm + 2 * 128 * 72, dsm + 2 * 128 * 72 + 64 * 72};

    int z = blockIdx.z;
    const __nv_bfloat16* Xg = g_Xb;
    const __nv_bfloat16* Wg = g_Wb[z];
    const float* bias = (z == 0) ? bq : (z == 1) ? bk : bv;
    __nv_bfloat16* C = g_QKV[z];

    int row0 = blockIdx.y * 128;
    int col0 = blockIdx.x * 64;
    int tid  = threadIdx.x;
    int warp = tid >> 5, lane = tid & 31;
    int g = lane >> 2, t4 = lane & 3;
    int wm = (warp & 3) * 32;
    int wn = (warp >> 2) * 32;

    int a_r = ((lane >> 3) & 1) * 8 + (lane & 7);
    int a_c = (lane >> 4) * 8;
    int v_r = (lane & 7) + ((lane >> 3) & 1) * 8;
    int v_s = lane >> 4;

    int xrw[4], xce[4];
    #pragma unroll
    for (int it = 0; it < 4; ++it) {
        int c = tid + it * 256;
        xrw[it] = c >> 3; xce[it] = (c & 7) * 8;
    }
    int wrw[2], wce[2];
    #pragma unroll
    for (int it = 0; it < 2; ++it) {
        int c = tid + it * 256;
        wrw[it] = c >> 3; wce[it] = (c & 7) * 8;
    }

    auto stage = [&](int kit, int buf) {
        int k0 = kit * 64;
        #pragma unroll
        for (int it = 0; it < 4; ++it)
            cpa16(&Xs[buf][xrw[it] * 72 + xce[it]],
                  Xg + (size_t)(row0 + xrw[it]) * DD + k0 + xce[it]);
        #pragma unroll
        for (int it = 0; it < 2; ++it)
            cpa16(&Ws[buf][wrw[it] * 72 + wce[it]],
                  Wg + (size_t)(k0 + wrw[it]) * DD + col0 + wce[it]);
    };

    float acc[2][4][4] = {};

    stage(0, 0); CP_COMMIT;

    for (int it = 0; it < 8; ++it) {
        int buf = it & 1;
        if (it < 7) { stage(it + 1, buf ^ 1); CP_COMMIT; CP_WAIT1; }
        else        { CP_WAIT0; }
        __syncthreads();

        #pragma unroll
        for (int ch = 0; ch < 4; ++ch) {
            int kk = ch * 16;
            uint32_t a[2][4];
            ldm_x4(a[0], &Xs[buf][(wm + a_r) * 72 + kk + a_c]);
            ldm_x4(a[1], &Xs[buf][(wm + 16 + a_r) * 72 + kk + a_c]);
            uint32_t b0[4], b1[4];
            ldm_x4_trans(b0, &Ws[buf][(kk + v_r) * 72 + wn + v_s * 8]);
            ldm_x4_trans(b1, &Ws[buf][(kk + v_r) * 72 + wn + 16 + v_s * 8]);
            #pragma unroll
            for (int m = 0; m < 2; ++m) {
                mma16(acc[m][0], a[m], b0[0], b0[1], acc[m][0]);
                mma16(acc[m][1], a[m], b0[2], b0[3], acc[m][1]);
                mma16(acc[m][2], a[m], b1[0], b1[1], acc[m][2]);
                mma16(acc[m][3], a[m], b1[2], b1[3], acc[m][3]);
            }
        }
        __syncthreads();
    }

    #pragma unroll
    for (int n = 0; n < 4; ++n) {
        int col = col0 + wn + n * 8 + 2 * t4;
        float2 bb = *(const float2*)(bias + col);
        #pragma unroll
        for (int m = 0; m < 2; ++m) {
            int r0 = row0 + wm + m * 16 + g;
            *(uint32_t*)(C + (size_t)r0 * DD + col) =
                pack_bf16(acc[m][n][0] + bb.x, acc[m][n][1] + bb.y);
            *(uint32_t*)(C + (size_t)(r0 + 8) * DD + col) =
                pack_bf16(acc[m][n][2] + bb.x, acc[m][n][3] + bb.y);
        }
    }
}

// ---------------------------------------------------------------------------
// Kernel 2: c[row] = (x[row] . w_g[D:2D]) * log2e
// ---------------------------------------------------------------------------
__global__ __launch_bounds__(256)
void gate_kernel(const float* __restrict__ x, const float* __restrict__ wg)
{
    int row  = blockIdx.x * 8 + (threadIdx.x >> 5);
    int lane = threadIdx.x & 31;
    const float* xr = x + (size_t)row * DD;
    const float* w2 = wg + DD;
    float s = 0.f;
    #pragma unroll 4
    for (int d = lane; d < DD; d += 32) s = fmaf(xr[d], w2[d], s);
    #pragma unroll
    for (int off = 16; off > 0; off >>= 1)
        s += __shfl_xor_sync(0xffffffffu, s, off);
    if (lane == 0) g_c[row] = s * LOG2E;
}

// ---------------------------------------------------------------------------
// Kernel B1: blocks 0..15 -> g_maxk[b][h] = max_j ||k_j||;
//            blocks 16..17 -> g_maxc[b] = max_j c_j (already log2-scaled).
// ---------------------------------------------------------------------------
__global__ __launch_bounds__(256)
void bounds1_kernel()
{
    __shared__ float red[256];
    int blk = blockIdx.x, tid = threadIdx.x;
    float mx = -1e30f;
    if (blk < 16) {
        int b = blk >> 3, h = blk & 7;
        const __nv_bfloat16* Kg = g_QKV[1] + (size_t)b * NN * DD + h * HD;
        for (int j = tid; j < NN; j += 256) {
            const __nv_bfloat16* kr = Kg + (size_t)j * DD;
            float s = 0.f;
            #pragma unroll
            for (int d = 0; d < HD; d += 2) {
                float2 f = __bfloat1622float2(*(const __nv_bfloat162*)(kr + d));
                s = fmaf(f.x, f.x, fmaf(f.y, f.y, s));
            }
            mx = fmaxf(mx, s);
        }
    } else {
        int b = blk - 16;
        for (int j = tid; j < NN; j += 256)
            mx = fmaxf(mx, g_c[b * NN + j]);
    }
    red[tid] = mx;
    __syncthreads();
    for (int st = 128; st > 0; st >>= 1) {
        if (tid < st) red[tid] = fmaxf(red[tid], red[tid + st]);
        __syncthreads();
    }
    if (tid == 0) {
        if (blk < 16) g_maxk[blk] = sqrtf(red[0]);
        else          g_maxc[blk - 16] = red[0];
    }
}

// ---------------------------------------------------------------------------
// Kernel B2: g_mrow[(b,h,i)] = SCLOG * ||q_i|| * maxk[b,h] + maxc[b] + 1
// One warp per row; 8 warps per block.
// ---------------------------------------------------------------------------
__global__ __launch_bounds__(256)
void bounds2_kernel()
{
    int gw   = (blockIdx.x * 256 + threadIdx.x) >> 5;   // 0 .. BB*HH*NN-1
    int lane = threadIdx.x & 31;
    int b = gw >> 14;            // HH*NN = 16384
    int h = (gw >> 11) & 7;      // NN = 2048
    int i = gw & 2047;
    const __nv_bfloat16* qr = g_QKV[0] + ((size_t)b * NN + i) * DD + h * HD;
    float2 f = __bfloat1622float2(*(const __nv_bfloat162*)(qr + 2 * lane));
    float s = fmaf(f.x, f.x, f.y * f.y);
    #pragma unroll
    for (int off = 16; off > 0; off >>= 1)
        s += __shfl_xor_sync(0xffffffffu, s, off);
    if (lane == 0)
        g_mrow[gw] = SCLOG * sqrtf(s) * g_maxk[b * 8 + h] + g_maxc[b] + 1.0f;
}

// ---------------------------------------------------------------------------
// Kernel 3: flash attention, bf16 mma, triple-buffered cp.async, P in
// registers. STATIC per-row exponent bound (g_mrow) instead of online
// softmax: no row-max shuffles, no O rescaling, no l rescaling in the loop;
// per-thread l partials reduced once at the end. Softmax invariant under the
// shift, so the result is mathematically identical.
// CTA = (64-query tile, h, b), 128 threads = 4 warps x 16 query rows.
// ---------------------------------------------------------------------------
__global__ __launch_bounds__(128, 4)
void attn_kernel(const float* __restrict__ x, const float* __restrict__ adj,
                 float* __restrict__ out)
{
    extern __shared__ __nv_bfloat16 asm_buf[];
    const int TB = 64 * 72;
    __nv_bfloat16* Kb0 = asm_buf;            // K buffers 0..2
    __nv_bfloat16* Vb0 = asm_buf + 3 * TB;   // V buffers 0..2

    int tid  = threadIdx.x;
    int warp = tid >> 5, lane = tid & 31;
    int g = lane >> 2, t4 = lane & 3;
    int qr = warp * 16;
    int i0 = blockIdx.x * 64;
    int h  = blockIdx.y;
    int b  = blockIdx.z;

    int a_r = ((lane >> 3) & 1) * 8 + (lane & 7);   // A non-trans (Q)
    int a_c = (lane >> 4) * 8;
    int k_r = (lane >> 4) * 8 + (lane & 7);         // B non-trans (K)
    int k_c = ((lane >> 3) & 1) * 8;
    int v_r = (lane & 7) + ((lane >> 3) & 1) * 8;   // B trans (V)
    int v_s = lane >> 4;

    const __nv_bfloat16* Qg = g_QKV[0] + (size_t)b * NN * DD + h * HD;
    const __nv_bfloat16* Kg = g_QKV[1] + (size_t)b * NN * DD + h * HD;
    const __nv_bfloat16* Vg = g_QKV[2] + (size_t)b * NN * DD + h * HD;
    const float* cv   = g_c + b * NN;
    const float* adjb = adj + (size_t)b * NN * NN;

    int srw[4], sce[4];
    #pragma unroll
    for (int it = 0; it < 4; ++it) {
        int c = tid + it * 128;
        srw[it] = c >> 3; sce[it] = (c & 7) * 8;
    }

    auto stage_kv = [&](int jt, int buf) {
        int j0 = jt * 64;
        #pragma unroll
        for (int it = 0; it < 4; ++it) {
            cpa16(Kb0 + buf * TB + srw[it] * 72 + sce[it],
                  Kg + (size_t)(j0 + srw[it]) * DD + sce[it]);
            cpa16(Vb0 + buf * TB + srw[it] * 72 + sce[it],
                  Vg + (size_t)(j0 + srw[it]) * DD + sce[it]);
        }
    };

    // ---- Stage Q into V buffer 2 (free until iter 1's staging) ----
    __nv_bfloat16* Qs = Vb0 + 2 * TB;
    #pragma unroll
    for (int it = 0; it < 4; ++it) {
        uint4 v = *(const uint4*)(Qg + (size_t)(i0 + srw[it]) * DD + sce[it]);
        *(uint4*)&Qs[srw[it] * 72 + sce[it]] = v;
    }
    stage_kv(0, 0); CP_COMMIT;
    __syncthreads();

    uint32_t qa[4][4];
    #pragma unroll
    for (int ch = 0; ch < 4; ++ch)
        ldm_x4(qa[ch], &Qs[(qr + a_r) * 72 + ch * 16 + a_c]);
    // iter-0's block barrier protects Qs before iter-1 stages buffer 2.

    // per-row static exponent bounds
    int r0g = i0 + qr + g, r1g = r0g + 8;
    float m0 = g_mrow[((size_t)b * HH + h) * NN + r0g];
    float m1 = g_mrow[((size_t)b * HH + h) * NN + r1g];

    float rs0 = 0.f, rs1 = 0.f;   // per-thread l partials across ALL iterations
    float o[8][4] = {};

    for (int jt = 0; jt < NN / 64; ++jt) {
        int j0 = jt * 64;
        int buf = jt % 3;
        if (jt + 1 < NN / 64) { stage_kv(jt + 1, (jt + 1) % 3); CP_COMMIT; CP_WAIT1; }
        else                  { CP_WAIT0; }
        __syncthreads();

        const __nv_bfloat16* Kt = Kb0 + buf * TB;
        const __nv_bfloat16* Vt = Vb0 + buf * TB;

        // ---- S = Q K^T ----
        float s[8][4] = {};
        #pragma unroll
        for (int ch = 0; ch < 4; ++ch) {
            int kk = ch * 16;
            #pragma unroll
            for (int np = 0; np < 4; ++np) {
                uint32_t kb[4];
                ldm_x4(kb, &Kt[(np * 16 + k_r) * 72 + kk + k_c]);
                mma16(s[2 * np],     qa[ch], kb[0], kb[1], s[2 * np]);
                mma16(s[2 * np + 1], qa[ch], kb[2], kb[3], s[2 * np + 1]);
            }
        }

        // ---- p = (adj+eps) * 2^(s*SC + c - m)  (static m: no rescaling) ----
        uint32_t pa[4][4];
        #pragma unroll
        for (int ch = 0; ch < 4; ++ch) {
            #pragma unroll
            for (int w = 0; w < 2; ++w) {
                int n = 2 * ch + w;
                int jc = j0 + n * 8 + 2 * t4;
                float2 cc = *(const float2*)(cv + jc);
                float c0x = cc.x - m0, c0y = cc.y - m0;
                float c1x = cc.x - m1, c1y = cc.y - m1;
                float2 ad0 = *(const float2*)(adjb + (size_t)r0g * NN + jc);
                float2 ad1 = *(const float2*)(adjb + (size_t)r1g * NN + jc);
                float p00 = ex2f(fmaf(s[n][0], SCLOG, c0x)) * (ad0.x + 1e-9f);
                float p01 = ex2f(fmaf(s[n][1], SCLOG, c0y)) * (ad0.y + 1e-9f);
                float p10 = ex2f(fmaf(s[n][2], SCLOG, c1x)) * (ad1.x + 1e-9f);
                float p11 = ex2f(fmaf(s[n][3], SCLOG, c1y)) * (ad1.y + 1e-9f);
                rs0 += p00 + p01; rs1 += p10 + p11;
                pa[ch][2 * w]     = pack_bf16(p00, p01);
                pa[ch][2 * w + 1] = pack_bf16(p10, p11);
            }
        }

        // ---- O += P @ V (P from registers, no rescale ever) ----
        #pragma unroll
        for (int ch = 0; ch < 4; ++ch) {
            int kk = ch * 16;
            #pragma unroll
            for (int np = 0; np < 4; ++np) {
                uint32_t vb[4];
                ldm_x4_trans(vb, &Vt[(kk + v_r) * 72 + (2 * np + v_s) * 8]);
                mma16(o[2 * np],     pa[ch], vb[0], vb[1], o[2 * np]);
                mma16(o[2 * np + 1], pa[ch], vb[2], vb[3], o[2 * np + 1]);
            }
        }
    }

    // ---- single end-of-kernel l reduction ----
    rs0 += __shfl_xor_sync(0xffffffffu, rs0, 1);
    rs0 += __shfl_xor_sync(0xffffffffu, rs0, 2);
    rs1 += __shfl_xor_sync(0xffffffffu, rs1, 1);
    rs1 += __shfl_xor_sync(0xffffffffu, rs1, 2);

    // ---- epilogue: normalize + residual (fp32) ----
    float inv0 = __fdividef(1.0f, rs0);
    float inv1 = __fdividef(1.0f, rs1);
    #pragma unroll
    for (int n = 0; n < 8; ++n) {
        int col = h * HD + n * 8 + 2 * t4;
        float2 x0 = *(const float2*)(x + ((size_t)b * NN + r0g) * DD + col);
        float2 x1 = *(const float2*)(x + ((size_t)b * NN + r1g) * DD + col);
        float2 o0 = {fmaf(o[n][0], inv0, x0.x), fmaf(o[n][1], inv0, x0.y)};
        float2 o1 = {fmaf(o[n][2], inv1, x1.x), fmaf(o[n][3], inv1, x1.y)};
        *(float2*)(out + ((size_t)b * NN + r0g) * DD + col) = o0;
        *(float2*)(out + ((size_t)b * NN + r1g) * DD + col) = o1;
    }
}

// ---------------------------------------------------------------------------
extern "C" void kernel_launch(void* const* d_in, const int* in_sizes, int n_in,
                              void* d_out, int out_size)
{
    const float* x   = (const float*)d_in[0];
    const float* adj = (const float*)d_in[1];
    const float* Wq  = (const float*)d_in[2];
    const float* bq  = (const float*)d_in[3];
    const float* Wk  = (const float*)d_in[4];
    const float* bk  = (const float*)d_in[5];
    const float* Wv  = (const float*)d_in[6];
    const float* bv  = (const float*)d_in[7];
    const float* wg  = (const float*)d_in[8];
    // d_in[9] (b_g) cancels inside the softmax; unused.
    float* out = (float*)d_out;

    const int qkv_smem = (2 * 128 * 72 + 2 * 64 * 72) * 2;   // 55296 B
    cudaFuncSetAttribute((const void*)qkv_gemm,
                         cudaFuncAttributeMaxDynamicSharedMemorySize, qkv_smem);
    const int attn_smem = 6 * 64 * 72 * 2;                   // 55296 B
    cudaFuncSetAttribute((const void*)attn_kernel,
                         cudaFuncAttributeMaxDynamicSharedMemorySize, attn_smem);

    convert_kernel<<<1408, 256>>>(x, Wq, Wk, Wv);
    gate_kernel<<<ROWS / 8, 256>>>(x, wg);
    qkv_gemm<<<dim3(DD / 64, ROWS / 128, 3), 256, qkv_smem>>>(bq, bk, bv);
    bounds1_kernel<<<18, 256>>>();
    bounds2_kernel<<<BB * HH * NN / 8, 256>>>();
    attn_kernel<<<dim3(NN / 64, HH, BB), 128, attn_smem>>>(x, adj, out);
}

// round 10
// speedup vs baseline: 1.2455x; 1.2455x over previous
#include <cuda_runtime.h>
#include <cuda_bf16.h>
#include <cstdint>

#define BB 2
#define NN 2048
#define DD 512
#define HH 8
#define HD 64
#define ROWS (BB*NN)

// Scratch (no allocations allowed)
__device__ __nv_bfloat16 g_QKV[3][(size_t)ROWS * DD];   // Q,K,V projections
__device__ __nv_bfloat16 g_Xb[(size_t)ROWS * DD];       // x in bf16
__device__ __nv_bfloat16 g_Wb[3][(size_t)DD * DD];      // W_q/k/v in bf16
__device__ float g_c[ROWS];                             // gate vec (log2-scaled)
__device__ unsigned g_maxk_bits[BB * HH];               // max_j ||k_j||^2 (float bits)
__device__ unsigned g_maxc_bits[BB];                    // max_j c_j (monotone-encoded)

#define LOG2E 1.4426950408889634f
#define SCLOG (0.125f * LOG2E)

// ---------------------------------------------------------------------------
// helpers
// ---------------------------------------------------------------------------
__device__ __forceinline__ float ex2f(float x) {        // 2^x on MUFU
    float r;
    asm("ex2.approx.f32 %0, %1;" : "=f"(r) : "f"(x));
    return r;
}
__device__ __forceinline__ uint32_t pack_bf16(float lo, float hi) {
    uint32_t r;
    asm("cvt.rn.bf16x2.f32 %0, %1, %2;" : "=r"(r) : "f"(hi), "f"(lo));
    return r;
}
__device__ __forceinline__ unsigned enc_ord(float f) {  // monotone float->uint
    int i = __float_as_int(f);
    return (i < 0) ? ~(unsigned)i : ((unsigned)i | 0x80000000u);
}
__device__ __forceinline__ float dec_ord(unsigned u) {
    int i = (u & 0x80000000u) ? (int)(u & 0x7fffffffu) : (int)~u;
    return __int_as_float(i);
}
__device__ __forceinline__ void mma16(float* d, const uint32_t* a,
                                      uint32_t b0, uint32_t b1, const float* c) {
    asm("mma.sync.aligned.m16n8k16.row.col.f32.bf16.bf16.f32 "
        "{%0,%1,%2,%3}, {%4,%5,%6,%7}, {%8,%9}, {%10,%11,%12,%13};"
        : "=f"(d[0]), "=f"(d[1]), "=f"(d[2]), "=f"(d[3])
        : "r"(a[0]), "r"(a[1]), "r"(a[2]), "r"(a[3]),
          "r"(b0), "r"(b1),
          "f"(c[0]), "f"(c[1]), "f"(c[2]), "f"(c[3]));
}
__device__ __forceinline__ void ldm_x4(uint32_t* r, const void* ptr) {
    uint32_t a = (uint32_t)__cvta_generic_to_shared(ptr);
    asm volatile("ldmatrix.sync.aligned.m8n8.x4.shared.b16 "
                 "{%0,%1,%2,%3}, [%4];"
                 : "=r"(r[0]), "=r"(r[1]), "=r"(r[2]), "=r"(r[3]) : "r"(a));
}
__device__ __forceinline__ void ldm_x4_trans(uint32_t* r, const void* ptr) {
    uint32_t a = (uint32_t)__cvta_generic_to_shared(ptr);
    asm volatile("ldmatrix.sync.aligned.m8n8.x4.trans.shared.b16 "
                 "{%0,%1,%2,%3}, [%4];"
                 : "=r"(r[0]), "=r"(r[1]), "=r"(r[2]), "=r"(r[3]) : "r"(a));
}
__device__ __forceinline__ void cpa16(void* smem_dst, const void* gsrc) {
    uint32_t d = (uint32_t)__cvta_generic_to_shared(smem_dst);
    asm volatile("cp.async.cg.shared.global [%0], [%1], 16;" :: "r"(d), "l"(gsrc));
}
#define CP_COMMIT asm volatile("cp.async.commit_group;" ::: "memory")
#define CP_WAIT1  asm volatile("cp.async.wait_group 1;" ::: "memory")
#define CP_WAIT0  asm volatile("cp.async.wait_group 0;" ::: "memory")

// ---------------------------------------------------------------------------
// Kernel 0: one-shot fp32 -> bf16 conversion of x and W_q/k/v.
// ---------------------------------------------------------------------------
__global__ __launch_bounds__(256)
void convert_kernel(const float* __restrict__ X, const float* __restrict__ Wq,
                    const float* __restrict__ Wk, const float* __restrict__ Wv)
{
    int idx = blockIdx.x * 256 + threadIdx.x;
    const float* src;
    __nv_bfloat16* dst;
    size_t off;
    if (idx < 262144) {
        src = X; dst = g_Xb; off = (size_t)idx * 8;
    } else {
        int r = idx - 262144;
        int z = r >> 15;
        int o = r & 32767;
        src = (z == 0) ? Wq : (z == 1) ? Wk : Wv;
        dst = g_Wb[z]; off = (size_t)o * 8;
    }
    float4 v0 = *(const float4*)(src + off);
    float4 v1 = *(const float4*)(src + off + 4);
    uint4 u;
    u.x = pack_bf16(v0.x, v0.y);
    u.y = pack_bf16(v0.z, v0.w);
    u.z = pack_bf16(v1.x, v1.y);
    u.w = pack_bf16(v1.z, v1.w);
    *(uint4*)(dst + off) = u;
}

// ---------------------------------------------------------------------------
// Kernel 1: fused QKV projection, pure bf16, cp.async double-buffered, BK=64.
// ---------------------------------------------------------------------------
__global__ __launch_bounds__(256)
void qkv_gemm(const float* __restrict__ bq, const float* __restrict__ bk,
              const float* __restrict__ bv)
{
    extern __shared__ __nv_bfloat16 dsm[];
    __nv_bfloat16* Xs[2] = {dsm, dsm + 128 * 72};
    __nv_bfloat16* Ws[2] = {dsm + 2 * 128 * 72, dsm + 2 * 128 * 72 + 64 * 72};

    int z = blockIdx.z;
    const __nv_bfloat16* Xg = g_Xb;
    const __nv_bfloat16* Wg = g_Wb[z];
    const float* bias = (z == 0) ? bq : (z == 1) ? bk : bv;
    __nv_bfloat16* C = g_QKV[z];

    int row0 = blockIdx.y * 128;
    int col0 = blockIdx.x * 64;
    int tid  = threadIdx.x;
    int warp = tid >> 5, lane = tid & 31;
    int g = lane >> 2, t4 = lane & 3;
    int wm = (warp & 3) * 32;
    int wn = (warp >> 2) * 32;

    int a_r = ((lane >> 3) & 1) * 8 + (lane & 7);
    int a_c = (lane >> 4) * 8;
    int v_r = (lane & 7) + ((lane >> 3) & 1) * 8;
    int v_s = lane >> 4;

    int xrw[4], xce[4];
    #pragma unroll
    for (int it = 0; it < 4; ++it) {
        int c = tid + it * 256;
        xrw[it] = c >> 3; xce[it] = (c & 7) * 8;
    }
    int wrw[2], wce[2];
    #pragma unroll
    for (int it = 0; it < 2; ++it) {
        int c = tid + it * 256;
        wrw[it] = c >> 3; wce[it] = (c & 7) * 8;
    }

    auto stage = [&](int kit, int buf) {
        int k0 = kit * 64;
        #pragma unroll
        for (int it = 0; it < 4; ++it)
            cpa16(&Xs[buf][xrw[it] * 72 + xce[it]],
                  Xg + (size_t)(row0 + xrw[it]) * DD + k0 + xce[it]);
        #pragma unroll
        for (int it = 0; it < 2; ++it)
            cpa16(&Ws[buf][wrw[it] * 72 + wce[it]],
                  Wg + (size_t)(k0 + wrw[it]) * DD + col0 + wce[it]);
    };

    float acc[2][4][4] = {};

    stage(0, 0); CP_COMMIT;

    for (int it = 0; it < 8; ++it) {
        int buf = it & 1;
        if (it < 7) { stage(it + 1, buf ^ 1); CP_COMMIT; CP_WAIT1; }
        else        { CP_WAIT0; }
        __syncthreads();

        #pragma unroll
        for (int ch = 0; ch < 4; ++ch) {
            int kk = ch * 16;
            uint32_t a[2][4];
            ldm_x4(a[0], &Xs[buf][(wm + a_r) * 72 + kk + a_c]);
            ldm_x4(a[1], &Xs[buf][(wm + 16 + a_r) * 72 + kk + a_c]);
            uint32_t b0[4], b1[4];
            ldm_x4_trans(b0, &Ws[buf][(kk + v_r) * 72 + wn + v_s * 8]);
            ldm_x4_trans(b1, &Ws[buf][(kk + v_r) * 72 + wn + 16 + v_s * 8]);
            #pragma unroll
            for (int m = 0; m < 2; ++m) {
                mma16(acc[m][0], a[m], b0[0], b0[1], acc[m][0]);
                mma16(acc[m][1], a[m], b0[2], b0[3], acc[m][1]);
                mma16(acc[m][2], a[m], b1[0], b1[1], acc[m][2]);
                mma16(acc[m][3], a[m], b1[2], b1[3], acc[m][3]);
            }
        }
        __syncthreads();
    }

    #pragma unroll
    for (int n = 0; n < 4; ++n) {
        int col = col0 + wn + n * 8 + 2 * t4;
        float2 bb = *(const float2*)(bias + col);
        #pragma unroll
        for (int m = 0; m < 2; ++m) {
            int r0 = row0 + wm + m * 16 + g;
            *(uint32_t*)(C + (size_t)r0 * DD + col) =
                pack_bf16(acc[m][n][0] + bb.x, acc[m][n][1] + bb.y);
            *(uint32_t*)(C + (size_t)(r0 + 8) * DD + col) =
                pack_bf16(acc[m][n][2] + bb.x, acc[m][n][3] + bb.y);
        }
    }
}

// ---------------------------------------------------------------------------
// Kernel 2: c[row] = (x[row] . w_g[D:2D]) * log2e
// ---------------------------------------------------------------------------
__global__ __launch_bounds__(256)
void gate_kernel(const float* __restrict__ x, const float* __restrict__ wg)
{
    int row  = blockIdx.x * 8 + (threadIdx.x >> 5);
    int lane = threadIdx.x & 31;
    const float* xr = x + (size_t)row * DD;
    const float* w2 = wg + DD;
    float s = 0.f;
    #pragma unroll 4
    for (int d = lane; d < DD; d += 32) s = fmaf(xr[d], w2[d], s);
    #pragma unroll
    for (int off = 16; off > 0; off >>= 1)
        s += __shfl_xor_sync(0xffffffffu, s, off);
    if (lane == 0) g_c[row] = s * LOG2E;
}

// ---------------------------------------------------------------------------
// Kernel B0: reset the atomic maxima (runs every graph replay).
// ---------------------------------------------------------------------------
__global__ void init_bounds_kernel()
{
    int t = threadIdx.x;
    if (t < BB * HH) g_maxk_bits[t] = 0u;                 // ||k||^2 >= 0
    if (t < BB)      g_maxc_bits[t] = 0u;                 // encodes very-negative
}

// ---------------------------------------------------------------------------
// Kernel B1 (WIDE): blocks 0..127: per-(b,h) max ||k_j||^2 via block reduce +
// atomicMax on float bits (128 blocks x 256 thr = one thread per row).
// Blocks 128..129: per-batch max c_j (monotone-encoded atomicMax).
// ---------------------------------------------------------------------------
__global__ __launch_bounds__(256)
void bounds_kernel()
{
    __shared__ float red[256];
    int blk = blockIdx.x, tid = threadIdx.x;
    float mx;
    if (blk < 128) {
        int bh = blk >> 3;                 // 0..15
        int j  = (blk & 7) * 256 + tid;    // row 0..2047
        int b = bh >> 3, h = bh & 7;
        const __nv_bfloat16* kr = g_QKV[1] + ((size_t)b * NN + j) * DD + h * HD;
        float s = 0.f;
        #pragma unroll
        for (int d = 0; d < HD; d += 8) {
            uint4 u = *(const uint4*)(kr + d);
            float2 f0 = __bfloat1622float2(*(__nv_bfloat162*)&u.x);
            float2 f1 = __bfloat1622float2(*(__nv_bfloat162*)&u.y);
            float2 f2 = __bfloat1622float2(*(__nv_bfloat162*)&u.z);
            float2 f3 = __bfloat1622float2(*(__nv_bfloat162*)&u.w);
            s = fmaf(f0.x, f0.x, fmaf(f0.y, f0.y, s));
            s = fmaf(f1.x, f1.x, fmaf(f1.y, f1.y, s));
            s = fmaf(f2.x, f2.x, fmaf(f2.y, f2.y, s));
            s = fmaf(f3.x, f3.x, fmaf(f3.y, f3.y, s));
        }
        mx = s;
        red[tid] = mx;
        __syncthreads();
        for (int st = 128; st > 0; st >>= 1) {
            if (tid < st) red[tid] = fmaxf(red[tid], red[tid + st]);
            __syncthreads();
        }
        if (tid == 0) atomicMax(&g_maxk_bits[bh], __float_as_uint(red[0]));
    } else {
        int b = blk - 128;
        mx = -1e30f;
        for (int j = tid; j < NN; j += 256)
            mx = fmaxf(mx, g_c[b * NN + j]);
        red[tid] = mx;
        __syncthreads();
        for (int st = 128; st > 0; st >>= 1) {
            if (tid < st) red[tid] = fmaxf(red[tid], red[tid + st]);
            __syncthreads();
        }
        if (tid == 0) atomicMax(&g_maxc_bits[b], enc_ord(red[0]));
    }
}

// ---------------------------------------------------------------------------
// Kernel 3: flash attention, bf16 mma, triple-buffered cp.async, P in
// registers. Static per-row exponent bound m = SC*||q||*max||k|| + maxc + 1
// computed IN the prologue from the Q fragments (no bounds2 kernel): no
// row-max shuffles, no O/l rescaling in the loop; one l reduction at the end.
// CTA = (64-query tile, h, b), 128 threads = 4 warps x 16 query rows.
// ---------------------------------------------------------------------------
__global__ __launch_bounds__(128, 4)
void attn_kernel(const float* __restrict__ x, const float* __restrict__ adj,
                 float* __restrict__ out)
{
    extern __shared__ __nv_bfloat16 asm_buf[];
    const int TB = 64 * 72;
    __nv_bfloat16* Kb0 = asm_buf;            // K buffers 0..2
    __nv_bfloat16* Vb0 = asm_buf + 3 * TB;   // V buffers 0..2

    int tid  = threadIdx.x;
    int warp = tid >> 5, lane = tid & 31;
    int g = lane >> 2, t4 = lane & 3;
    int qr = warp * 16;
    int i0 = blockIdx.x * 64;
    int h  = blockIdx.y;
    int b  = blockIdx.z;

    int a_r = ((lane >> 3) & 1) * 8 + (lane & 7);   // A non-trans (Q)
    int a_c = (lane >> 4) * 8;
    int k_r = (lane >> 4) * 8 + (lane & 7);         // B non-trans (K)
    int k_c = ((lane >> 3) & 1) * 8;
    int v_r = (lane & 7) + ((lane >> 3) & 1) * 8;   // B trans (V)
    int v_s = lane >> 4;

    const __nv_bfloat16* Qg = g_QKV[0] + (size_t)b * NN * DD + h * HD;
    const __nv_bfloat16* Kg = g_QKV[1] + (size_t)b * NN * DD + h * HD;
    const __nv_bfloat16* Vg = g_QKV[2] + (size_t)b * NN * DD + h * HD;
    const float* cv   = g_c + b * NN;
    const float* adjb = adj + (size_t)b * NN * NN;

    int srw[4], sce[4];
    #pragma unroll
    for (int it = 0; it < 4; ++it) {
        int c = tid + it * 128;
        srw[it] = c >> 3; sce[it] = (c & 7) * 8;
    }

    auto stage_kv = [&](int jt, int buf) {
        int j0 = jt * 64;
        #pragma unroll
        for (int it = 0; it < 4; ++it) {
            cpa16(Kb0 + buf * TB + srw[it] * 72 + sce[it],
                  Kg + (size_t)(j0 + srw[it]) * DD + sce[it]);
            cpa16(Vb0 + buf * TB + srw[it] * 72 + sce[it],
                  Vg + (size_t)(j0 + srw[it]) * DD + sce[it]);
        }
    };

    // ---- Stage Q into V buffer 2 (free until iter 1's staging) ----
    __nv_bfloat16* Qs = Vb0 + 2 * TB;
    #pragma unroll
    for (int it = 0; it < 4; ++it) {
        uint4 v = *(const uint4*)(Qg + (size_t)(i0 + srw[it]) * DD + sce[it]);
        *(uint4*)&Qs[srw[it] * 72 + sce[it]] = v;
    }
    stage_kv(0, 0); CP_COMMIT;
    __syncthreads();

    uint32_t qa[4][4];
    #pragma unroll
    for (int ch = 0; ch < 4; ++ch)
        ldm_x4(qa[ch], &Qs[(qr + a_r) * 72 + ch * 16 + a_c]);
    // iter-0's block barrier protects Qs before iter-1 stages buffer 2.

    // ---- per-row ||q|| from fragments (rows live in 4-lane groups) ----
    float nq0 = 0.f, nq1 = 0.f;
    #pragma unroll
    for (int ch = 0; ch < 4; ++ch) {
        float2 f;
        f = __bfloat1622float2(*(__nv_bfloat162*)&qa[ch][0]);
        nq0 = fmaf(f.x, f.x, fmaf(f.y, f.y, nq0));
        f = __bfloat1622float2(*(__nv_bfloat162*)&qa[ch][2]);
        nq0 = fmaf(f.x, f.x, fmaf(f.y, f.y, nq0));
        f = __bfloat1622float2(*(__nv_bfloat162*)&qa[ch][1]);
        nq1 = fmaf(f.x, f.x, fmaf(f.y, f.y, nq1));
        f = __bfloat1622float2(*(__nv_bfloat162*)&qa[ch][3]);
        nq1 = fmaf(f.x, f.x, fmaf(f.y, f.y, nq1));
    }
    nq0 += __shfl_xor_sync(0xffffffffu, nq0, 1);
    nq0 += __shfl_xor_sync(0xffffffffu, nq0, 2);
    nq1 += __shfl_xor_sync(0xffffffffu, nq1, 1);
    nq1 += __shfl_xor_sync(0xffffffffu, nq1, 2);

    float maxk = sqrtf(__uint_as_float(g_maxk_bits[b * HH + h]));
    float maxc = dec_ord(g_maxc_bits[b]);
    float m0 = SCLOG * sqrtf(nq0) * maxk + maxc + 1.0f;
    float m1 = SCLOG * sqrtf(nq1) * maxk + maxc + 1.0f;

    int r0g = i0 + qr + g, r1g = r0g + 8;
    float rs0 = 0.f, rs1 = 0.f;   // per-thread l partials across ALL iterations
    float o[8][4] = {};

    for (int jt = 0; jt < NN / 64; ++jt) {
        int j0 = jt * 64;
        int buf = jt % 3;
        if (jt + 1 < NN / 64) { stage_kv(jt + 1, (jt + 1) % 3); CP_COMMIT; CP_WAIT1; }
        else                  { CP_WAIT0; }
        __syncthreads();

        const __nv_bfloat16* Kt = Kb0 + buf * TB;
        const __nv_bfloat16* Vt = Vb0 + buf * TB;

        // ---- S = Q K^T ----
        float s[8][4] = {};
        #pragma unroll
        for (int ch = 0; ch < 4; ++ch) {
            int kk = ch * 16;
            #pragma unroll
            for (int np = 0; np < 4; ++np) {
                uint32_t kb[4];
                ldm_x4(kb, &Kt[(np * 16 + k_r) * 72 + kk + k_c]);
                mma16(s[2 * np],     qa[ch], kb[0], kb[1], s[2 * np]);
                mma16(s[2 * np + 1], qa[ch], kb[2], kb[3], s[2 * np + 1]);
            }
        }

        // ---- p = (adj+eps) * 2^(s*SC + c - m)  (static m: no rescaling) ----
        uint32_t pa[4][4];
        #pragma unroll
        for (int ch = 0; ch < 4; ++ch) {
            #pragma unroll
            for (int w = 0; w < 2; ++w) {
                int n = 2 * ch + w;
                int jc = j0 + n * 8 + 2 * t4;
                float2 cc = *(const float2*)(cv + jc);
                float c0x = cc.x - m0, c0y = cc.y - m0;
                float c1x = cc.x - m1, c1y = cc.y - m1;
                float2 ad0 = *(const float2*)(adjb + (size_t)r0g * NN + jc);
                float2 ad1 = *(const float2*)(adjb + (size_t)r1g * NN + jc);
                float p00 = ex2f(fmaf(s[n][0], SCLOG, c0x)) * (ad0.x + 1e-9f);
                float p01 = ex2f(fmaf(s[n][1], SCLOG, c0y)) * (ad0.y + 1e-9f);
                float p10 = ex2f(fmaf(s[n][2], SCLOG, c1x)) * (ad1.x + 1e-9f);
                float p11 = ex2f(fmaf(s[n][3], SCLOG, c1y)) * (ad1.y + 1e-9f);
                rs0 += p00 + p01; rs1 += p10 + p11;
                pa[ch][2 * w]     = pack_bf16(p00, p01);
                pa[ch][2 * w + 1] = pack_bf16(p10, p11);
            }
        }

        // ---- O += P @ V (P from registers, no rescale ever) ----
        #pragma unroll
        for (int ch = 0; ch < 4; ++ch) {
            int kk = ch * 16;
            #pragma unroll
            for (int np = 0; np < 4; ++np) {
                uint32_t vb[4];
                ldm_x4_trans(vb, &Vt[(kk + v_r) * 72 + (2 * np + v_s) * 8]);
                mma16(o[2 * np],     pa[ch], vb[0], vb[1], o[2 * np]);
                mma16(o[2 * np + 1], pa[ch], vb[2], vb[3], o[2 * np + 1]);
            }
        }
    }

    // ---- single end-of-kernel l reduction ----
    rs0 += __shfl_xor_sync(0xffffffffu, rs0, 1);
    rs0 += __shfl_xor_sync(0xffffffffu, rs0, 2);
    rs1 += __shfl_xor_sync(0xffffffffu, rs1, 1);
    rs1 += __shfl_xor_sync(0xffffffffu, rs1, 2);

    // ---- epilogue: normalize + residual (fp32) ----
    float inv0 = __fdividef(1.0f, rs0);
    float inv1 = __fdividef(1.0f, rs1);
    #pragma unroll
    for (int n = 0; n < 8; ++n) {
        int col = h * HD + n * 8 + 2 * t4;
        float2 x0 = *(const float2*)(x + ((size_t)b * NN + r0g) * DD + col);
        float2 x1 = *(const float2*)(x + ((size_t)b * NN + r1g) * DD + col);
        float2 o0 = {fmaf(o[n][0], inv0, x0.x), fmaf(o[n][1], inv0, x0.y)};
        float2 o1 = {fmaf(o[n][2], inv1, x1.x), fmaf(o[n][3], inv1, x1.y)};
        *(float2*)(out + ((size_t)b * NN + r0g) * DD + col) = o0;
        *(float2*)(out + ((size_t)b * NN + r1g) * DD + col) = o1;
    }
}

// ---------------------------------------------------------------------------
extern "C" void kernel_launch(void* const* d_in, const int* in_sizes, int n_in,
                              void* d_out, int out_size)
{
    const float* x   = (const float*)d_in[0];
    const float* adj = (const float*)d_in[1];
    const float* Wq  = (const float*)d_in[2];
    const float* bq  = (const float*)d_in[3];
    const float* Wk  = (const float*)d_in[4];
    const float* bk  = (const float*)d_in[5];
    const float* Wv  = (const float*)d_in[6];
    const float* bv  = (const float*)d_in[7];
    const float* wg  = (const float*)d_in[8];
    // d_in[9] (b_g) cancels inside the softmax; unused.
    float* out = (float*)d_out;

    const int qkv_smem = (2 * 128 * 72 + 2 * 64 * 72) * 2;   // 55296 B
    cudaFuncSetAttribute((const void*)qkv_gemm,
                         cudaFuncAttributeMaxDynamicSharedMemorySize, qkv_smem);
    const int attn_smem = 6 * 64 * 72 * 2;                   // 55296 B
    cudaFuncSetAttribute((const void*)attn_kernel,
                         cudaFuncAttributeMaxDynamicSharedMemorySize, attn_smem);

    convert_kernel<<<1408, 256>>>(x, Wq, Wk, Wv);
    gate_kernel<<<ROWS / 8, 256>>>(x, wg);
    init_bounds_kernel<<<1, 32>>>();
    qkv_gemm<<<dim3(DD / 64, ROWS / 128, 3), 256, qkv_smem>>>(bq, bk, bv);
    bounds_kernel<<<130, 256>>>();
    attn_kernel<<<dim3(NN / 64, HH, BB), 128, attn_smem>>>(x, adj, out);
}